// round 1
// baseline (speedup 1.0000x reference)
#include <cuda_runtime.h>
#include <math.h>

#define BB 16384
#define NN 20
#define DD 128
#define HH 4
#define DM 384
#define DK 96
#define SCALE 0.1020620726159658f /* 1/sqrt(96) */

// ---------------- device scratch (no allocations allowed) ----------------
__device__ float g_qt[(size_t)BB * 1536];   // q-tilde [b][h*384+j]
__device__ float g_c [(size_t)BB * 1536];   // context [b][h*384+j]
__device__ float g_ao[(size_t)BB * 384];    // attn_out (pre-fc) [b][i]
__device__ float g_ln[(size_t)BB * 384];    // LayerNorm output [b][i]
__device__ float g_WqT[256 * 384];          // [m_eff][i]  (m_eff: 0..127 src, 128..255 time)
__device__ float g_WvT[4 * 384 * 96];       // [h][j][d]
__device__ float g_fcT[384 * 384];          // [k][i]
__device__ float g_m1T[512 * 128];          // [k][r]
__device__ float g_m2T[128 * 128];          // [k][r]

// ---------------- weight transposes ----------------
__global__ void k_prep(const float* __restrict__ Wq, const float* __restrict__ Wv,
                       const float* __restrict__ fc_w, const float* __restrict__ m1_w,
                       const float* __restrict__ m2_w) {
    int i = blockIdx.x * 256 + threadIdx.x;
    if (i < 98304) { // WqT: 256x384
        int m = i / 384, c = i % 384;
        g_WqT[i] = Wq[c * 384 + (m < 128 ? m : m + 128)];
        return;
    }
    i -= 98304;
    if (i < 147456) { // WvT: [h][j][d]
        int h = i / (384 * 96);
        int r = i % (384 * 96);
        int j = r / 96, d = r % 96;
        g_WvT[i] = Wv[(h * 96 + d) * 384 + j];
        return;
    }
    i -= 147456;
    if (i < 147456) { // fcT
        int k = i / 384, c = i % 384;
        g_fcT[i] = fc_w[c * 384 + k];
        return;
    }
    i -= 147456;
    if (i < 65536) { // m1T
        int k = i / 128, r = i % 128;
        g_m1T[i] = m1_w[r * 512 + k];
        return;
    }
    i -= 65536;
    if (i < 16384) { // m2T
        int k = i / 128, r = i % 128;
        g_m2T[i] = m2_w[r * 128 + k];
        return;
    }
}

// ---------------- q projection + q-tilde, 64 batch rows per block ----------------
// smem: sa[64*256] | qs[64*384] | sb[32*96]   = 176128 bytes
__global__ void __launch_bounds__(256) k_qproj(const float* __restrict__ src,
                                               const float* __restrict__ src_ts,
                                               const float* __restrict__ freq,
                                               const float* __restrict__ phase,
                                               const float* __restrict__ Wk) {
    extern __shared__ float sm[];
    float* sa = sm;                 // 64 x 256 (q_in effective)
    float* qs = sm + 64 * 256;      // 64 x 384 (q)
    float* sb = qs + 64 * 384;      // 32 x 96
    const int tid = threadIdx.x;
    const int b0 = blockIdx.x * 64;
    const int ct = tid & 31;  // column lane
    const int rt = tid >> 5;  // row group (8 rows each)

    // load A = [src | cos(src_ts*freq+phase)]
    for (int idx = tid; idx < 64 * 256; idx += 256) {
        int r = idx >> 8, m = idx & 255;
        float v;
        if (m < 128) v = src[(b0 + r) * 128 + m];
        else { int d = m - 128; v = cosf(src_ts[b0 + r] * freq[d] + phase[d]); }
        sa[idx] = v;
    }
    __syncthreads();

    // phase 1: qs(64x384) = sa(64x256) @ WqT(256x384), 4 passes of 96 cols
    for (int pass = 0; pass < 4; ++pass) {
        const int c0 = pass * 96;
        float acc[8][3];
        #pragma unroll
        for (int r = 0; r < 8; ++r) { acc[r][0] = 0.f; acc[r][1] = 0.f; acc[r][2] = 0.f; }
        for (int kt = 0; kt < 256; kt += 32) {
            __syncthreads();
            for (int idx = tid; idx < 3072; idx += 256) {
                int kk = idx / 96, c = idx % 96;
                sb[idx] = g_WqT[(kt + kk) * 384 + c0 + c];
            }
            __syncthreads();
            #pragma unroll
            for (int kk = 0; kk < 32; ++kk) {
                float bf0 = sb[kk * 96 + ct];
                float bf1 = sb[kk * 96 + ct + 32];
                float bf2 = sb[kk * 96 + ct + 64];
                #pragma unroll
                for (int r = 0; r < 8; ++r) {
                    float a = sa[(rt * 8 + r) * 256 + kt + kk];
                    acc[r][0] = fmaf(a, bf0, acc[r][0]);
                    acc[r][1] = fmaf(a, bf1, acc[r][1]);
                    acc[r][2] = fmaf(a, bf2, acc[r][2]);
                }
            }
        }
        #pragma unroll
        for (int r = 0; r < 8; ++r)
            #pragma unroll
            for (int cc = 0; cc < 3; ++cc)
                qs[(rt * 8 + r) * 384 + c0 + ct + 32 * cc] = acc[r][cc];
    }
    __syncthreads();

    // phase 2: for each head, qt_h(64x384) = q_h(64x96) @ Wk_h(96x384)
    for (int h = 0; h < 4; ++h) {
        for (int pass = 0; pass < 4; ++pass) {
            const int c0 = pass * 96;
            float acc[8][3];
            #pragma unroll
            for (int r = 0; r < 8; ++r) { acc[r][0] = 0.f; acc[r][1] = 0.f; acc[r][2] = 0.f; }
            for (int kt = 0; kt < 96; kt += 32) {
                __syncthreads();
                for (int idx = tid; idx < 3072; idx += 256) {
                    int kk = idx / 96, c = idx % 96;
                    sb[idx] = Wk[(h * 96 + kt + kk) * 384 + c0 + c];
                }
                __syncthreads();
                #pragma unroll
                for (int kk = 0; kk < 32; ++kk) {
                    float bf0 = sb[kk * 96 + ct];
                    float bf1 = sb[kk * 96 + ct + 32];
                    float bf2 = sb[kk * 96 + ct + 64];
                    #pragma unroll
                    for (int r = 0; r < 8; ++r) {
                        float a = qs[(rt * 8 + r) * 384 + h * 96 + kt + kk];
                        acc[r][0] = fmaf(a, bf0, acc[r][0]);
                        acc[r][1] = fmaf(a, bf1, acc[r][1]);
                        acc[r][2] = fmaf(a, bf2, acc[r][2]);
                    }
                }
            }
            #pragma unroll
            for (int r = 0; r < 8; ++r)
                #pragma unroll
                for (int cc = 0; cc < 3; ++cc)
                    g_qt[(size_t)(b0 + rt * 8 + r) * 1536 + h * 384 + c0 + ct + 32 * cc] = acc[r][cc];
        }
    }
}

// ---------------- attention core: one block per batch element ----------------
__global__ void __launch_bounds__(256) k_attn(const float* __restrict__ seq,
                                              const float* __restrict__ seq_e,
                                              const float* __restrict__ seq_ts,
                                              const unsigned int* __restrict__ mask,
                                              const float* __restrict__ freq,
                                              const float* __restrict__ phase,
                                              float* __restrict__ attn_out) {
    __shared__ float kin[NN * 384];
    __shared__ float qts[1536];
    __shared__ float sc[HH][NN];
    __shared__ float pp[HH][NN];
    const int b = blockIdx.x;
    const int tid = threadIdx.x;
    const int w = tid >> 5, lane = tid & 31;

    // build k_in = [seq | seq_e | cos(seq_ts*freq+phase)]
    for (int idx = tid; idx < NN * 128; idx += 256) {
        int n = idx >> 7, d = idx & 127;
        kin[n * 384 + d]       = seq  [((size_t)b * NN + n) * 128 + d];
        kin[n * 384 + 128 + d] = seq_e[((size_t)b * NN + n) * 128 + d];
        kin[n * 384 + 256 + d] = cosf(seq_ts[b * NN + n] * freq[d] + phase[d]);
    }
    for (int idx = tid; idx < 1536; idx += 256)
        qts[idx] = g_qt[(size_t)b * 1536 + idx];
    __syncthreads();

    // scores: 80 (h,n) pairs, one warp per pair
    for (int p = w; p < HH * NN; p += 8) {
        int h = p / NN, n = p % NN;
        float partial = 0.f;
        for (int j = lane; j < 384; j += 32)
            partial = fmaf(qts[h * 384 + j], kin[n * 384 + j], partial);
        #pragma unroll
        for (int off = 16; off; off >>= 1)
            partial += __shfl_xor_sync(0xffffffffu, partial, off);
        if (lane == 0) {
            float s = partial * SCALE;
            if (mask[b * NN + n] != 0u) s = -1.0e10f;
            sc[h][n] = s;
        }
    }
    __syncthreads();

    // softmax per head (warp per head)
    if (w < HH) {
        float v = (lane < NN) ? sc[w][lane] : -3.0e38f;
        float mx = v;
        #pragma unroll
        for (int off = 16; off; off >>= 1)
            mx = fmaxf(mx, __shfl_xor_sync(0xffffffffu, mx, off));
        float e = (lane < NN) ? expf(v - mx) : 0.f;
        float s = e;
        #pragma unroll
        for (int off = 16; off; off >>= 1)
            s += __shfl_xor_sync(0xffffffffu, s, off);
        float prob = e / s;
        if (lane < NN) {
            pp[w][lane] = prob;
            attn_out[((size_t)w * BB + b) * NN + lane] = prob;
        }
    }
    __syncthreads();

    // context c[h][j] = sum_n p[h][n] * kin[n][j]
    for (int idx = tid; idx < 1536; idx += 256) {
        int h = idx / 384, j = idx - h * 384;
        float s = 0.f;
        #pragma unroll
        for (int n = 0; n < NN; ++n)
            s = fmaf(pp[h][n], kin[n * 384 + j], s);
        g_c[(size_t)b * 1536 + idx] = s;
    }
}

// ---------------- per-head Wv apply: attn_out(B,384) ----------------
__global__ void __launch_bounds__(256) k_vout() {
    __shared__ float sa[64 * 32];
    __shared__ float sb[32 * 96];
    const int tid = threadIdx.x;
    const int b0 = blockIdx.x * 64;
    const int ct = tid & 31;
    const int rt = tid >> 5;

    for (int h = 0; h < 4; ++h) {
        float acc[8][3];
        #pragma unroll
        for (int r = 0; r < 8; ++r) { acc[r][0] = 0.f; acc[r][1] = 0.f; acc[r][2] = 0.f; }
        for (int kt = 0; kt < 384; kt += 32) {
            __syncthreads();
            for (int idx = tid; idx < 2048; idx += 256) {
                int r = idx >> 5, kk = idx & 31;
                sa[idx] = g_c[(size_t)(b0 + r) * 1536 + h * 384 + kt + kk];
            }
            for (int idx = tid; idx < 3072; idx += 256) {
                int kk = idx / 96, c = idx % 96;
                sb[idx] = g_WvT[h * (384 * 96) + (kt + kk) * 96 + c];
            }
            __syncthreads();
            #pragma unroll
            for (int kk = 0; kk < 32; ++kk) {
                float bf0 = sb[kk * 96 + ct];
                float bf1 = sb[kk * 96 + ct + 32];
                float bf2 = sb[kk * 96 + ct + 64];
                #pragma unroll
                for (int r = 0; r < 8; ++r) {
                    float a = sa[(rt * 8 + r) * 32 + kk];
                    acc[r][0] = fmaf(a, bf0, acc[r][0]);
                    acc[r][1] = fmaf(a, bf1, acc[r][1]);
                    acc[r][2] = fmaf(a, bf2, acc[r][2]);
                }
            }
        }
        #pragma unroll
        for (int r = 0; r < 8; ++r)
            #pragma unroll
            for (int cc = 0; cc < 3; ++cc)
                g_ao[(size_t)(b0 + rt * 8 + r) * 384 + h * 96 + ct + 32 * cc] = acc[r][cc];
    }
}

// ---------------- fc + bias + residual(q_in) + LayerNorm ----------------
__global__ void __launch_bounds__(256) k_fcln(const float* __restrict__ src,
                                              const float* __restrict__ src_ts,
                                              const float* __restrict__ freq,
                                              const float* __restrict__ phase,
                                              const float* __restrict__ fc_b,
                                              const float* __restrict__ ln_g,
                                              const float* __restrict__ ln_b) {
    __shared__ float sa[16 * 32];
    __shared__ float sb[32 * 96];
    __shared__ float ob[16 * 384];
    const int tid = threadIdx.x;
    const int b0 = blockIdx.x * 16;
    const int ct = tid & 31;
    const int rt = tid >> 5;  // 8 groups x 2 rows

    for (int pass = 0; pass < 4; ++pass) {
        const int c0 = pass * 96;
        float acc[2][3];
        acc[0][0]=acc[0][1]=acc[0][2]=acc[1][0]=acc[1][1]=acc[1][2]=0.f;
        for (int kt = 0; kt < 384; kt += 32) {
            __syncthreads();
            for (int idx = tid; idx < 512; idx += 256) {
                int r = idx >> 5, kk = idx & 31;
                sa[idx] = g_ao[(size_t)(b0 + r) * 384 + kt + kk];
            }
            for (int idx = tid; idx < 3072; idx += 256) {
                int kk = idx / 96, c = idx % 96;
                sb[idx] = g_fcT[(kt + kk) * 384 + c0 + c];
            }
            __syncthreads();
            #pragma unroll
            for (int kk = 0; kk < 32; ++kk) {
                float bf0 = sb[kk * 96 + ct];
                float bf1 = sb[kk * 96 + ct + 32];
                float bf2 = sb[kk * 96 + ct + 64];
                #pragma unroll
                for (int r = 0; r < 2; ++r) {
                    float a = sa[(rt * 2 + r) * 32 + kk];
                    acc[r][0] = fmaf(a, bf0, acc[r][0]);
                    acc[r][1] = fmaf(a, bf1, acc[r][1]);
                    acc[r][2] = fmaf(a, bf2, acc[r][2]);
                }
            }
        }
        #pragma unroll
        for (int r = 0; r < 2; ++r) {
            int row = rt * 2 + r;
            #pragma unroll
            for (int cc = 0; cc < 3; ++cc) {
                int col = c0 + ct + 32 * cc;
                float v = acc[r][cc] + fc_b[col];
                if (col < 128) v += src[(size_t)(b0 + row) * 128 + col];
                else if (col >= 256) {
                    int d = col - 256;
                    v += cosf(src_ts[b0 + row] * freq[d] + phase[d]);
                }
                ob[row * 384 + col] = v;
            }
        }
    }
    __syncthreads();

    // LayerNorm: warp w handles rows 2w, 2w+1
    const int w = tid >> 5, lane = tid & 31;
    for (int rr = 0; rr < 2; ++rr) {
        int row = w * 2 + rr;
        float s1 = 0.f, s2 = 0.f;
        for (int j = lane; j < 384; j += 32) {
            float v = ob[row * 384 + j];
            s1 += v; s2 = fmaf(v, v, s2);
        }
        #pragma unroll
        for (int off = 16; off; off >>= 1) {
            s1 += __shfl_xor_sync(0xffffffffu, s1, off);
            s2 += __shfl_xor_sync(0xffffffffu, s2, off);
        }
        float mu = s1 * (1.f / 384.f);
        float var = s2 * (1.f / 384.f) - mu * mu;
        float inv = rsqrtf(var + 1e-5f);
        for (int j = lane; j < 384; j += 32) {
            float v = ob[row * 384 + j];
            g_ln[(size_t)(b0 + row) * 384 + j] = (v - mu) * inv * ln_g[j] + ln_b[j];
        }
    }
}

// ---------------- MLP: concat -> relu(512->128) -> 128->128 ----------------
// smem: xs[32*512] | hs[32*128] | sb[32*128] = 98304 bytes
__global__ void __launch_bounds__(256) k_mlp(const float* __restrict__ src,
                                             const float* __restrict__ m1_b,
                                             const float* __restrict__ m2_b,
                                             float* __restrict__ y) {
    extern __shared__ float sm[];
    float* xs = sm;               // 32 x 512
    float* hs = sm + 32 * 512;    // 32 x 128
    float* sb = hs + 32 * 128;    // 32 x 128
    const int tid = threadIdx.x;
    const int b0 = blockIdx.x * 32;
    const int ct = tid & 31;
    const int rt = tid >> 5;  // 8 groups x 4 rows

    for (int idx = tid; idx < 32 * 512; idx += 256) {
        int r = idx >> 9, k = idx & 511;
        xs[idx] = (k < 384) ? g_ln[(size_t)(b0 + r) * 384 + k]
                            : src[(size_t)(b0 + r) * 128 + (k - 384)];
    }

    float acc[4][4];
    #pragma unroll
    for (int r = 0; r < 4; ++r)
        #pragma unroll
        for (int c = 0; c < 4; ++c) acc[r][c] = 0.f;

    for (int kt = 0; kt < 512; kt += 32) {
        __syncthreads();
        for (int idx = tid; idx < 4096; idx += 256) {
            int kk = idx >> 7, c = idx & 127;
            sb[idx] = g_m1T[(kt + kk) * 128 + c];
        }
        __syncthreads();
        #pragma unroll
        for (int kk = 0; kk < 32; ++kk) {
            float bf[4];
            #pragma unroll
            for (int cc = 0; cc < 4; ++cc) bf[cc] = sb[kk * 128 + ct + 32 * cc];
            #pragma unroll
            for (int r = 0; r < 4; ++r) {
                float a = xs[(rt * 4 + r) * 512 + kt + kk];
                #pragma unroll
                for (int cc = 0; cc < 4; ++cc) acc[r][cc] = fmaf(a, bf[cc], acc[r][cc]);
            }
        }
    }
    #pragma unroll
    for (int r = 0; r < 4; ++r)
        #pragma unroll
        for (int cc = 0; cc < 4; ++cc) {
            int col = ct + 32 * cc;
            hs[(rt * 4 + r) * 128 + col] = fmaxf(acc[r][cc] + m1_b[col], 0.f);
        }

    float acc2[4][4];
    #pragma unroll
    for (int r = 0; r < 4; ++r)
        #pragma unroll
        for (int c = 0; c < 4; ++c) acc2[r][c] = 0.f;

    for (int kt = 0; kt < 128; kt += 32) {
        __syncthreads();
        for (int idx = tid; idx < 4096; idx += 256) {
            int kk = idx >> 7, c = idx & 127;
            sb[idx] = g_m2T[(kt + kk) * 128 + c];
        }
        __syncthreads();
        #pragma unroll
        for (int kk = 0; kk < 32; ++kk) {
            float bf[4];
            #pragma unroll
            for (int cc = 0; cc < 4; ++cc) bf[cc] = sb[kk * 128 + ct + 32 * cc];
            #pragma unroll
            for (int r = 0; r < 4; ++r) {
                float a = hs[(rt * 4 + r) * 128 + kt + kk];
                #pragma unroll
                for (int cc = 0; cc < 4; ++cc) acc2[r][cc] = fmaf(a, bf[cc], acc2[r][cc]);
            }
        }
    }
    #pragma unroll
    for (int r = 0; r < 4; ++r)
        #pragma unroll
        for (int cc = 0; cc < 4; ++cc) {
            int col = ct + 32 * cc;
            y[(size_t)(b0 + rt * 4 + r) * 128 + col] = acc2[r][cc] + m2_b[col];
        }
}

// ---------------- launch ----------------
extern "C" void kernel_launch(void* const* d_in, const int* in_sizes, int n_in,
                              void* d_out, int out_size) {
    const float* src    = (const float*)d_in[0];
    const float* seq    = (const float*)d_in[1];
    const float* seq_e  = (const float*)d_in[2];
    const float* src_ts = (const float*)d_in[3];
    const float* seq_ts = (const float*)d_in[4];
    const unsigned int* mask = (const unsigned int*)d_in[5];
    const float* freq   = (const float*)d_in[6];
    const float* phase  = (const float*)d_in[7];
    const float* Wq     = (const float*)d_in[8];
    const float* Wk     = (const float*)d_in[9];
    const float* Wv     = (const float*)d_in[10];
    const float* fc_w   = (const float*)d_in[11];
    const float* fc_b   = (const float*)d_in[12];
    const float* ln_g   = (const float*)d_in[13];
    const float* ln_b   = (const float*)d_in[14];
    const float* m1_w   = (const float*)d_in[15];
    const float* m1_b   = (const float*)d_in[16];
    const float* m2_w   = (const float*)d_in[17];
    const float* m2_b   = (const float*)d_in[18];

    float* y_out = (float*)d_out;
    float* attn_out = y_out + (size_t)BB * DD;

    cudaFuncSetAttribute(k_qproj, cudaFuncAttributeMaxDynamicSharedMemorySize, 176128);
    cudaFuncSetAttribute(k_mlp,   cudaFuncAttributeMaxDynamicSharedMemorySize, 98304);

    k_prep <<<1856, 256>>>(Wq, Wv, fc_w, m1_w, m2_w);
    k_qproj<<<BB / 64, 256, 176128>>>(src, src_ts, freq, phase, Wk);
    k_attn <<<BB, 256>>>(seq, seq_e, seq_ts, mask, freq, phase, attn_out);
    k_vout <<<BB / 64, 256>>>();
    k_fcln <<<BB / 16, 256>>>(src, src_ts, freq, phase, fc_b, ln_g, ln_b);
    k_mlp  <<<BB / 32, 256, 98304>>>(src, m1_b, m2_b, y_out);
}

// round 2
// speedup vs baseline: 1.3089x; 1.3089x over previous
#include <cuda_runtime.h>
#include <math.h>

#define BB 16384
#define NN 20
#define DD 128
#define HH 4
#define SCALE 0.1020620726159658f /* 1/sqrt(96) */

typedef unsigned long long u64;

// packed f32x2 helpers (FFMA2 — not emitted by ptxas from C++)
#define PK2(o, lo, hi) \
    asm("mov.b64 %0, {%1, %2};" : "=l"(o) : "r"(__float_as_uint(lo)), "r"(__float_as_uint(hi)))
#define FMA2(d, a, b, c) \
    asm("fma.rn.f32x2 %0, %1, %2, %3;" : "=l"(d) : "l"(a), "l"(b), "l"(c))
#define UPK2(lo, hi, v) do { unsigned int _ul, _uh; \
    asm("mov.b64 {%0, %1}, %2;" : "=r"(_ul), "=r"(_uh) : "l"(v)); \
    lo = __uint_as_float(_ul); hi = __uint_as_float(_uh); } while (0)

// ---------------- device scratch ----------------
__device__ float g_qt[(size_t)BB * 1536];   // q-tilde [b][h*384+j]
__device__ float g_c [(size_t)BB * 1536];   // context [b][h*384+j]
__device__ float g_ao[(size_t)BB * 384];    // attn out pre-fc
__device__ float g_pre[(size_t)BB * 384];   // fc+bias+residual (pre-LN)
__device__ float g_WqT[256 * 384];
__device__ float g_WvT[4 * 384 * 96];
__device__ float g_fcT[384 * 384];
__device__ float g_m1T[512 * 128];
__device__ float g_m2T[128 * 128];

// ---------------- weight transposes ----------------
__global__ void k_prep(const float* __restrict__ Wq, const float* __restrict__ Wv,
                       const float* __restrict__ fc_w, const float* __restrict__ m1_w,
                       const float* __restrict__ m2_w) {
    int i = blockIdx.x * 256 + threadIdx.x;
    if (i < 98304) { int m = i / 384, c = i % 384;
        g_WqT[i] = Wq[c * 384 + (m < 128 ? m : m + 128)]; return; }
    i -= 98304;
    if (i < 147456) { int h = i / 36864, r = i % 36864, j = r / 96, d = r % 96;
        g_WvT[i] = Wv[(h * 96 + d) * 384 + j]; return; }
    i -= 147456;
    if (i < 147456) { int k = i / 384, c = i % 384;
        g_fcT[i] = fc_w[c * 384 + k]; return; }
    i -= 147456;
    if (i < 65536) { int k = i / 128, r = i % 128;
        g_m1T[i] = m1_w[r * 512 + k]; return; }
    i -= 65536;
    if (i < 16384) { int k = i / 128, r = i % 128;
        g_m2T[i] = m2_w[r * 128 + k]; return; }
}

// ============ GEMM inner: 64 rows x 96 cols tile, thread = 8 rows x 3 cols ============
// sa: [32 k][?] staged row-major [row][32]; sb: [32 k][96 cols]
// acc[p][c] = f32x2 over row pair (rt*8+2p, rt*8+2p+1)
#define GEMM_INNER(ACC, SA, SASTRIDE, SB, CT, RT)                         \
    _Pragma("unroll")                                                     \
    for (int kk = 0; kk < 32; ++kk) {                                     \
        float b0 = SB[kk * 96 + CT];                                      \
        float b1 = SB[kk * 96 + CT + 32];                                 \
        float b2 = SB[kk * 96 + CT + 64];                                 \
        u64 bp0, bp1, bp2;                                                \
        PK2(bp0, b0, b0); PK2(bp1, b1, b1); PK2(bp2, b2, b2);             \
        _Pragma("unroll")                                                 \
        for (int p = 0; p < 4; ++p) {                                     \
            float a0 = SA[(RT * 8 + 2 * p) * SASTRIDE + kk];              \
            float a1 = SA[(RT * 8 + 2 * p + 1) * SASTRIDE + kk];          \
            u64 ap; PK2(ap, a0, a1);                                      \
            FMA2(ACC[p][0], ap, bp0, ACC[p][0]);                          \
            FMA2(ACC[p][1], ap, bp1, ACC[p][1]);                          \
            FMA2(ACC[p][2], ap, bp2, ACC[p][2]);                          \
        }                                                                 \
    }

// ---------------- q projection + q-tilde: block = (64-batch tile, head) ----------------
__global__ void __launch_bounds__(256) k_qproj(const float* __restrict__ src,
                                               const float* __restrict__ src_ts,
                                               const float* __restrict__ freq,
                                               const float* __restrict__ phase,
                                               const float* __restrict__ Wk) {
    __shared__ float sa[64 * 32];
    __shared__ float qs[64 * 96];
    __shared__ float sb[32 * 96];
    __shared__ float sts[64];
    const int tid = threadIdx.x;
    const int ct = tid & 31, rt = tid >> 5;
    const int bt = blockIdx.x >> 2;
    const int h  = blockIdx.x & 3;
    const int b0 = bt * 64;
    const int c0h = h * 96;

    if (tid < 64) sts[tid] = src_ts[b0 + tid];

    // phase 1: qs(64x96) = A(64x256) @ WqT[:, h*96 : h*96+96]
    u64 acc[4][3];
    #pragma unroll
    for (int p = 0; p < 4; ++p) { acc[p][0] = 0ull; acc[p][1] = 0ull; acc[p][2] = 0ull; }
    for (int kt = 0; kt < 256; kt += 32) {
        __syncthreads();
        const int m = kt + ct;
        for (int rr = rt; rr < 64; rr += 8) {
            float v;
            if (m < 128) v = src[(size_t)(b0 + rr) * 128 + m];
            else { int d = m - 128; v = cosf(sts[rr] * freq[d] + phase[d]); }
            sa[rr * 32 + ct] = v;
        }
        for (int idx = tid; idx < 3072; idx += 256) {
            int kk = idx / 96, c = idx - kk * 96;
            sb[idx] = g_WqT[(kt + kk) * 384 + c0h + c];
        }
        __syncthreads();
        GEMM_INNER(acc, sa, 32, sb, ct, rt)
    }
    __syncthreads();
    #pragma unroll
    for (int p = 0; p < 4; ++p)
        #pragma unroll
        for (int cc = 0; cc < 3; ++cc) {
            float lo, hi; UPK2(lo, hi, acc[p][cc]);
            qs[(rt * 8 + 2 * p) * 96 + ct + 32 * cc] = lo;
            qs[(rt * 8 + 2 * p + 1) * 96 + ct + 32 * cc] = hi;
        }

    // phase 2: qt(64x384) = qs(64x96) @ Wk_h(96x384), 4 col passes
    for (int pass = 0; pass < 4; ++pass) {
        const int c0 = pass * 96;
        u64 a2[4][3];
        #pragma unroll
        for (int p = 0; p < 4; ++p) { a2[p][0] = 0ull; a2[p][1] = 0ull; a2[p][2] = 0ull; }
        for (int kt = 0; kt < 96; kt += 32) {
            __syncthreads();
            for (int idx = tid; idx < 3072; idx += 256) {
                int kk = idx / 96, c = idx - kk * 96;
                sb[idx] = Wk[(h * 96 + kt + kk) * 384 + c0 + c];
            }
            __syncthreads();
            GEMM_INNER(a2, (qs + kt), 96, sb, ct, rt)
        }
        #pragma unroll
        for (int p = 0; p < 4; ++p)
            #pragma unroll
            for (int cc = 0; cc < 3; ++cc) {
                float lo, hi; UPK2(lo, hi, a2[p][cc]);
                g_qt[(size_t)(b0 + rt * 8 + 2 * p) * 1536 + h * 384 + c0 + ct + 32 * cc] = lo;
                g_qt[(size_t)(b0 + rt * 8 + 2 * p + 1) * 1536 + h * 384 + c0 + ct + 32 * cc] = hi;
            }
    }
}

// ---------------- attention core: one block per batch element ----------------
__global__ void __launch_bounds__(256) k_attn(const float* __restrict__ seq,
                                              const float* __restrict__ seq_e,
                                              const float* __restrict__ seq_ts,
                                              const unsigned int* __restrict__ mask,
                                              const float* __restrict__ freq,
                                              const float* __restrict__ phase,
                                              float* __restrict__ attn_out) {
    __shared__ float kin[NN * 384];
    __shared__ float qts[1536];
    __shared__ float sc[HH][NN];
    __shared__ float pp[HH][NN];
    const int b = blockIdx.x;
    const int tid = threadIdx.x;
    const int w = tid >> 5, lane = tid & 31;

    const float4* seq4   = (const float4*)seq;
    const float4* seq_e4 = (const float4*)seq_e;
    for (int idx = tid; idx < NN * 32; idx += 256) {
        int n = idx >> 5, q = idx & 31;
        float4 a = seq4  [((size_t)b * NN + n) * 32 + q];
        float4 e = seq_e4[((size_t)b * NN + n) * 32 + q];
        *(float4*)&kin[n * 384 + q * 4]       = a;
        *(float4*)&kin[n * 384 + 128 + q * 4] = e;
    }
    for (int idx = tid; idx < NN * 128; idx += 256) {
        int n = idx >> 7, d = idx & 127;
        kin[n * 384 + 256 + d] = cosf(seq_ts[b * NN + n] * freq[d] + phase[d]);
    }
    const float4* qt4 = (const float4*)(g_qt + (size_t)b * 1536);
    for (int idx = tid; idx < 384; idx += 256)
        *(float4*)&qts[idx * 4] = qt4[idx];
    __syncthreads();

    for (int p = w; p < HH * NN; p += 8) {
        int h = p / NN, n = p - h * NN;
        float partial = 0.f;
        #pragma unroll
        for (int t = 0; t < 12; ++t)
            partial = fmaf(qts[h * 384 + lane + 32 * t], kin[n * 384 + lane + 32 * t], partial);
        #pragma unroll
        for (int off = 16; off; off >>= 1)
            partial += __shfl_xor_sync(0xffffffffu, partial, off);
        if (lane == 0) {
            float s = partial * SCALE;
            if (mask[b * NN + n] != 0u) s = -1.0e10f;
            sc[h][n] = s;
        }
    }
    __syncthreads();

    if (w < HH) {
        float v = (lane < NN) ? sc[w][lane] : -3.0e38f;
        float mx = v;
        #pragma unroll
        for (int off = 16; off; off >>= 1)
            mx = fmaxf(mx, __shfl_xor_sync(0xffffffffu, mx, off));
        float e = (lane < NN) ? expf(v - mx) : 0.f;
        float s = e;
        #pragma unroll
        for (int off = 16; off; off >>= 1)
            s += __shfl_xor_sync(0xffffffffu, s, off);
        float prob = e / s;
        if (lane < NN) {
            pp[w][lane] = prob;
            attn_out[((size_t)w * BB + b) * NN + lane] = prob;
        }
    }
    __syncthreads();

    for (int idx = tid; idx < 1536; idx += 256) {
        int h = idx / 384, j = idx - h * 384;
        float s = 0.f;
        #pragma unroll
        for (int n = 0; n < NN; ++n)
            s = fmaf(pp[h][n], kin[n * 384 + j], s);
        g_c[(size_t)b * 1536 + idx] = s;
    }
}

// ---------------- Wv apply: block = (64-batch tile, head), K=384 ----------------
__global__ void __launch_bounds__(256) k_vout() {
    __shared__ float sa[64 * 32];
    __shared__ float sb[32 * 96];
    const int tid = threadIdx.x;
    const int ct = tid & 31, rt = tid >> 5;
    const int bt = blockIdx.x >> 2;
    const int h  = blockIdx.x & 3;
    const int b0 = bt * 64;

    u64 acc[4][3];
    #pragma unroll
    for (int p = 0; p < 4; ++p) { acc[p][0] = 0ull; acc[p][1] = 0ull; acc[p][2] = 0ull; }
    for (int kt = 0; kt < 384; kt += 32) {
        __syncthreads();
        for (int rr = rt; rr < 64; rr += 8)
            sa[rr * 32 + ct] = g_c[(size_t)(b0 + rr) * 1536 + h * 384 + kt + ct];
        for (int idx = tid; idx < 3072; idx += 256) {
            int kk = idx / 96, c = idx - kk * 96;
            sb[idx] = g_WvT[h * 36864 + (kt + kk) * 96 + c];
        }
        __syncthreads();
        GEMM_INNER(acc, sa, 32, sb, ct, rt)
    }
    #pragma unroll
    for (int p = 0; p < 4; ++p)
        #pragma unroll
        for (int cc = 0; cc < 3; ++cc) {
            float lo, hi; UPK2(lo, hi, acc[p][cc]);
            g_ao[(size_t)(b0 + rt * 8 + 2 * p) * 384 + h * 96 + ct + 32 * cc] = lo;
            g_ao[(size_t)(b0 + rt * 8 + 2 * p + 1) * 384 + h * 96 + ct + 32 * cc] = hi;
        }
}

// ---------------- fc + bias + residual -> g_pre: block = (64-batch tile, col quarter) ----------------
__global__ void __launch_bounds__(256) k_fc(const float* __restrict__ src,
                                            const float* __restrict__ src_ts,
                                            const float* __restrict__ freq,
                                            const float* __restrict__ phase,
                                            const float* __restrict__ fc_b) {
    __shared__ float sa[64 * 32];
    __shared__ float sb[32 * 96];
    const int tid = threadIdx.x;
    const int ct = tid & 31, rt = tid >> 5;
    const int bt = blockIdx.x >> 2;
    const int c0 = (blockIdx.x & 3) * 96;
    const int b0 = bt * 64;

    u64 acc[4][3];
    #pragma unroll
    for (int p = 0; p < 4; ++p) { acc[p][0] = 0ull; acc[p][1] = 0ull; acc[p][2] = 0ull; }
    for (int kt = 0; kt < 384; kt += 32) {
        __syncthreads();
        for (int rr = rt; rr < 64; rr += 8)
            sa[rr * 32 + ct] = g_ao[(size_t)(b0 + rr) * 384 + kt + ct];
        for (int idx = tid; idx < 3072; idx += 256) {
            int kk = idx / 96, c = idx - kk * 96;
            sb[idx] = g_fcT[(kt + kk) * 384 + c0 + c];
        }
        __syncthreads();
        GEMM_INNER(acc, sa, 32, sb, ct, rt)
    }
    #pragma unroll
    for (int p = 0; p < 4; ++p)
        #pragma unroll
        for (int cc = 0; cc < 3; ++cc) {
            float lo, hi; UPK2(lo, hi, acc[p][cc]);
            const int col = c0 + ct + 32 * cc;
            float res_lo = 0.f, res_hi = 0.f;
            int r_lo = b0 + rt * 8 + 2 * p, r_hi = r_lo + 1;
            if (col < 128) {
                res_lo = src[(size_t)r_lo * 128 + col];
                res_hi = src[(size_t)r_hi * 128 + col];
            } else if (col >= 256) {
                int d = col - 256;
                res_lo = cosf(src_ts[r_lo] * freq[d] + phase[d]);
                res_hi = cosf(src_ts[r_hi] * freq[d] + phase[d]);
            }
            g_pre[(size_t)r_lo * 384 + col] = lo + fc_b[col] + res_lo;
            g_pre[(size_t)r_hi * 384 + col] = hi + fc_b[col] + res_hi;
        }
}

// ---------------- fused LayerNorm + MLP: 32 rows/block ----------------
__global__ void __launch_bounds__(256) k_mlpln(const float* __restrict__ src,
                                               const float* __restrict__ ln_g,
                                               const float* __restrict__ ln_b,
                                               const float* __restrict__ m1_b,
                                               const float* __restrict__ m2_b,
                                               float* __restrict__ y) {
    extern __shared__ float sm[];
    float* xs = sm;               // 32 x 512
    float* hs = sm + 32 * 512;    // 32 x 128
    float* sb = hs + 32 * 128;    // 32 x 128
    const int tid = threadIdx.x;
    const int ct = tid & 31, rt = tid >> 5;
    const int b0 = blockIdx.x * 32;
    const int w = rt, lane = ct;

    for (int idx = tid; idx < 32 * 384; idx += 256) {
        int r = idx / 384, c = idx - r * 384;
        xs[r * 512 + c] = g_pre[(size_t)(b0 + r) * 384 + c];
    }
    for (int idx = tid; idx < 32 * 128; idx += 256) {
        int r = idx >> 7, d = idx & 127;
        xs[r * 512 + 384 + d] = src[(size_t)(b0 + r) * 128 + d];
    }
    __syncthreads();

    // LayerNorm on cols [0,384) of each row; warp w handles rows 4w..4w+3
    for (int rr = 0; rr < 4; ++rr) {
        int row = w * 4 + rr;
        float s1 = 0.f, s2 = 0.f;
        #pragma unroll
        for (int t = 0; t < 12; ++t) {
            float v = xs[row * 512 + lane + 32 * t];
            s1 += v; s2 = fmaf(v, v, s2);
        }
        #pragma unroll
        for (int off = 16; off; off >>= 1) {
            s1 += __shfl_xor_sync(0xffffffffu, s1, off);
            s2 += __shfl_xor_sync(0xffffffffu, s2, off);
        }
        float mu = s1 * (1.f / 384.f);
        float var = s2 * (1.f / 384.f) - mu * mu;
        float inv = rsqrtf(var + 1e-5f);
        #pragma unroll
        for (int t = 0; t < 12; ++t) {
            int j = lane + 32 * t;
            float v = xs[row * 512 + j];
            xs[row * 512 + j] = (v - mu) * inv * ln_g[j] + ln_b[j];
        }
    }
    __syncthreads();

    // GEMM1: hs(32x128) = relu(xs(32x512) @ m1T + b). thread = 4 rows x 4 cols
    u64 acc[2][4];
    #pragma unroll
    for (int p = 0; p < 2; ++p)
        #pragma unroll
        for (int c = 0; c < 4; ++c) acc[p][c] = 0ull;
    for (int kt = 0; kt < 512; kt += 32) {
        __syncthreads();
        for (int idx = tid; idx < 4096; idx += 256) {
            int kk = idx >> 7, c = idx & 127;
            sb[idx] = g_m1T[(kt + kk) * 128 + c];
        }
        __syncthreads();
        #pragma unroll
        for (int kk = 0; kk < 32; ++kk) {
            u64 bp[4];
            #pragma unroll
            for (int c = 0; c < 4; ++c) {
                float bv = sb[kk * 128 + ct + 32 * c];
                PK2(bp[c], bv, bv);
            }
            #pragma unroll
            for (int p = 0; p < 2; ++p) {
                float a0 = xs[(rt * 4 + 2 * p) * 512 + kt + kk];
                float a1 = xs[(rt * 4 + 2 * p + 1) * 512 + kt + kk];
                u64 ap; PK2(ap, a0, a1);
                #pragma unroll
                for (int c = 0; c < 4; ++c) FMA2(acc[p][c], ap, bp[c], acc[p][c]);
            }
        }
    }
    __syncthreads();
    #pragma unroll
    for (int p = 0; p < 2; ++p)
        #pragma unroll
        for (int c = 0; c < 4; ++c) {
            float lo, hi; UPK2(lo, hi, acc[p][c]);
            int col = ct + 32 * c;
            hs[(rt * 4 + 2 * p) * 128 + col] = fmaxf(lo + m1_b[col], 0.f);
            hs[(rt * 4 + 2 * p + 1) * 128 + col] = fmaxf(hi + m1_b[col], 0.f);
        }

    // GEMM2: y = hs(32x128) @ m2T + b
    u64 a2[2][4];
    #pragma unroll
    for (int p = 0; p < 2; ++p)
        #pragma unroll
        for (int c = 0; c < 4; ++c) a2[p][c] = 0ull;
    for (int kt = 0; kt < 128; kt += 32) {
        __syncthreads();
        for (int idx = tid; idx < 4096; idx += 256) {
            int kk = idx >> 7, c = idx & 127;
            sb[idx] = g_m2T[(kt + kk) * 128 + c];
        }
        __syncthreads();
        #pragma unroll
        for (int kk = 0; kk < 32; ++kk) {
            u64 bp[4];
            #pragma unroll
            for (int c = 0; c < 4; ++c) {
                float bv = sb[kk * 128 + ct + 32 * c];
                PK2(bp[c], bv, bv);
            }
            #pragma unroll
            for (int p = 0; p < 2; ++p) {
                float a0 = hs[(rt * 4 + 2 * p) * 128 + kt + kk];
                float a1 = hs[(rt * 4 + 2 * p + 1) * 128 + kt + kk];
                u64 ap; PK2(ap, a0, a1);
                #pragma unroll
                for (int c = 0; c < 4; ++c) FMA2(a2[p][c], ap, bp[c], a2[p][c]);
            }
        }
    }
    #pragma unroll
    for (int p = 0; p < 2; ++p)
        #pragma unroll
        for (int c = 0; c < 4; ++c) {
            float lo, hi; UPK2(lo, hi, a2[p][c]);
            int col = ct + 32 * c;
            y[(size_t)(b0 + rt * 4 + 2 * p) * 128 + col] = lo + m2_b[col];
            y[(size_t)(b0 + rt * 4 + 2 * p + 1) * 128 + col] = hi + m2_b[col];
        }
}

// ---------------- launch ----------------
extern "C" void kernel_launch(void* const* d_in, const int* in_sizes, int n_in,
                              void* d_out, int out_size) {
    const float* src    = (const float*)d_in[0];
    const float* seq    = (const float*)d_in[1];
    const float* seq_e  = (const float*)d_in[2];
    const float* src_ts = (const float*)d_in[3];
    const float* seq_ts = (const float*)d_in[4];
    const unsigned int* mask = (const unsigned int*)d_in[5];
    const float* freq   = (const float*)d_in[6];
    const float* phase  = (const float*)d_in[7];
    const float* Wq     = (const float*)d_in[8];
    const float* Wk     = (const float*)d_in[9];
    const float* Wv     = (const float*)d_in[10];
    const float* fc_w   = (const float*)d_in[11];
    const float* fc_b   = (const float*)d_in[12];
    const float* ln_g   = (const float*)d_in[13];
    const float* ln_b   = (const float*)d_in[14];
    const float* m1_w   = (const float*)d_in[15];
    const float* m1_b   = (const float*)d_in[16];
    const float* m2_w   = (const float*)d_in[17];
    const float* m2_b   = (const float*)d_in[18];

    float* y_out = (float*)d_out;
    float* attn_out = y_out + (size_t)BB * DD;

    cudaFuncSetAttribute(k_mlpln, cudaFuncAttributeMaxDynamicSharedMemorySize, 98304);

    k_prep  <<<1856, 256>>>(Wq, Wv, fc_w, m1_w, m2_w);
    k_qproj <<<1024, 256>>>(src, src_ts, freq, phase, Wk);
    k_attn  <<<BB, 256>>>(seq, seq_e, seq_ts, mask, freq, phase, attn_out);
    k_vout  <<<1024, 256>>>();
    k_fc    <<<1024, 256>>>(src, src_ts, freq, phase, fc_b);
    k_mlpln <<<BB / 32, 256, 98304>>>(src, ln_g, ln_b, m1_b, m2_b, y_out);
}